// round 14
// baseline (speedup 1.0000x reference)
#include <cuda_runtime.h>
#include <cuda_bf16.h>
#include <math.h>
#include <stdint.h>

#define B_  32768
#define C_  1024
#define CH_ 256
#define RANK_ 16

// ---------------- scratch (device globals; no allocation allowed) ------------
__device__ __nv_bfloat16 g_z [B_ * C_];     // LN output
__device__ __nv_bfloat16 g_u [B_ * CH_];    // GLU output
__device__ __nv_bfloat16 g_p [B_ * CH_];    // gelu output

__device__ __nv_bfloat16 g_Wglu[C_ * 512];  // [K=1024][512] interleaved 8d|8g per 16
__device__ __nv_bfloat16 g_W1b [CH_ * CH_]; // [K=256][N=256] dw-folded W1
__device__ __nv_bfloat16 g_Wtb [CH_ * C_];  // [K=256][N=1024] 0.5*Wtail (bf16)

__device__ float g_fWvo[CH_ * CH_];
__device__ float g_fW23[CH_ * CH_];
__device__ float g_fT1 [CH_ * RANK_];
__device__ float g_fWuE[CH_ * C_];
__device__ float g_b1p[CH_], g_bvo[CH_], g_t16[RANK_], g_b23[CH_], g_buE[C_], g_bt[C_];

__device__ __forceinline__ float warp_sum(float s) {
#pragma unroll
    for (int o = 16; o; o >>= 1) s += __shfl_xor_sync(0xFFFFFFFFu, s, o);
    return s;
}

// ---------------- prepA body --------------------------------------------------
#define A_FWVO 0
#define A_FT1  65536
#define A_B1P  196608
#define A_BVO  204800
#define A_T16  212992
#define A_W1B  213504
#define A_WGLU 279040
#define A_TOT  803328
#define A_BLOCKS (A_TOT / 256)   // 3138
#define LN_BLOCKS (B_ / 8)       // 4096

__device__ void prepA_body(int i,
                      const float* __restrict__ Wv, const float* __restrict__ Wo,
                      const float* __restrict__ bo, const float* __restrict__ Wu,
                      const float* __restrict__ Wld, const float* __restrict__ dw_w,
                      const float* __restrict__ dw_b, const float* __restrict__ W1,
                      const float* __restrict__ b1, const float* __restrict__ bv,
                      const float* __restrict__ bu, const float* __restrict__ Wd,
                      const float* __restrict__ Wg) {
    int lane = i & 31;
    if (i < A_FT1) {
        int r = i >> 8, c = i & 255;
        float s = 0.f;
#pragma unroll 8
        for (int k = 0; k < CH_; k++) s += Wv[r * CH_ + k] * Wo[k * CH_ + c];
        g_fWvo[i] = s;
    } else if (i < A_B1P) {
        int w = (i - A_FT1) >> 5;
        int r = w >> 4, c = w & 15;
        float s = 0.f;
#pragma unroll
        for (int kk = 0; kk < 32; kk++) {
            int k = lane + kk * 32;
            s += Wu[r * C_ + k] * Wld[k * RANK_ + c];
        }
        s = warp_sum(s);
        if (lane == 0) g_fT1[w] = s;
    } else if (i < A_BVO) {
        int w = (i - A_B1P) >> 5;
        float s = 0.f;
#pragma unroll
        for (int kk = 0; kk < 8; kk++) {
            int k = lane + kk * 32;
            s += dw_b[k] * W1[k * CH_ + w];
        }
        s = warp_sum(s);
        if (lane == 0) g_b1p[w] = s + b1[w];
    } else if (i < A_T16) {
        int w = (i - A_BVO) >> 5;
        float s = 0.f;
#pragma unroll
        for (int kk = 0; kk < 8; kk++) {
            int k = lane + kk * 32;
            s += bv[k] * Wo[k * CH_ + w];
        }
        s = warp_sum(s);
        if (lane == 0) g_bvo[w] = s + bo[w];
    } else if (i < A_W1B) {
        int w = (i - A_T16) >> 5;
        float s = 0.f;
#pragma unroll
        for (int kk = 0; kk < 32; kk++) {
            int k = lane + kk * 32;
            s += bu[k] * Wld[k * RANK_ + w];
        }
        s = warp_sum(s);
        if (lane == 0) g_t16[w] = s;
    } else if (i < A_WGLU) {
        int j = i - A_W1B;
        int k = j >> 8, n = j & 255;
        g_W1b[j] = __float2bfloat16_rn(dw_w[k] * W1[k * CH_ + n]);
    } else if (i < A_TOT) {
        int j = i - A_WGLU;
        int k = j >> 9, F = j & 511;
        int grp = F >> 4, wi = F & 15;
        int col = grp * 8 + (wi & 7);
        float v = (wi < 8) ? Wd[k * CH_ + col] : Wg[k * CH_ + col];
        g_Wglu[j] = __float2bfloat16_rn(v);
    }
}

// ---------------- LN body: warp-per-row ---------------------------------------
__device__ void ln_body(int w, int lane,
                        const float* __restrict__ x, const float* __restrict__ gamma,
                        const float* __restrict__ beta, __nv_bfloat16* __restrict__ z) {
    const float4* px = (const float4*)(x + (size_t)w * C_);
    float4 v[8];
#pragma unroll
    for (int j = 0; j < 8; j++) v[j] = px[lane + j * 32];
    float s = 0.f, ss = 0.f;
#pragma unroll
    for (int j = 0; j < 8; j++) {
        s  += v[j].x + v[j].y + v[j].z + v[j].w;
        ss += v[j].x * v[j].x + v[j].y * v[j].y + v[j].z * v[j].z + v[j].w * v[j].w;
    }
    s  = warp_sum(s);
    ss = warp_sum(ss);
    float mean = s * (1.f / C_);
    float var  = ss * (1.f / C_) - mean * mean;
    float rstd = rsqrtf(var + 1e-5f);
    uint2* pz = (uint2*)(z + (size_t)w * C_);
    const float4* pg = (const float4*)gamma;
    const float4* pb = (const float4*)beta;
#pragma unroll
    for (int j = 0; j < 8; j++) {
        float4 gm = pg[lane + j * 32];
        float4 bt = pb[lane + j * 32];
        union { __nv_bfloat16 h[4]; uint2 u; } pk;
        pk.h[0] = __float2bfloat16_rn((v[j].x - mean) * rstd * gm.x + bt.x);
        pk.h[1] = __float2bfloat16_rn((v[j].y - mean) * rstd * gm.y + bt.y);
        pk.h[2] = __float2bfloat16_rn((v[j].z - mean) * rstd * gm.z + bt.z);
        pk.h[3] = __float2bfloat16_rn((v[j].w - mean) * rstd * gm.w + bt.w);
        pz[lane + j * 32] = pk.u;
    }
}

// ---------------- K1: LN + prepA ----------------------------------------------
__global__ __launch_bounds__(256)
void k1_prepA_ln(const float* __restrict__ Wv, const float* __restrict__ Wo,
                 const float* __restrict__ bo, const float* __restrict__ Wu,
                 const float* __restrict__ Wld, const float* __restrict__ dw_w,
                 const float* __restrict__ dw_b, const float* __restrict__ W1,
                 const float* __restrict__ b1, const float* __restrict__ bv,
                 const float* __restrict__ bu, const float* __restrict__ Wd,
                 const float* __restrict__ Wg,
                 const float* __restrict__ x, const float* __restrict__ ln_g,
                 const float* __restrict__ ln_b, __nv_bfloat16* __restrict__ z) {
    int bid = blockIdx.x;
    if (bid < LN_BLOCKS) {
        int w = bid * 8 + (threadIdx.x >> 5);
        ln_body(w, threadIdx.x & 31, x, ln_g, ln_b, z);
    } else {
        prepA_body((bid - LN_BLOCKS) * 256 + threadIdx.x, Wv, Wo, bo, Wu, Wld,
                   dw_w, dw_b, W1, b1, bv, bu, Wd, Wg);
    }
}

// ---------------- prepB body --------------------------------------------------
#define B_FWUE 65536
#define B_B23  327680
#define B_BUE  335872
#define B_TOT  336896
#define B_BLOCKS (B_TOT / 256)   // 1316

__device__ void prepB_body(int i, const float* __restrict__ W2,
                           const float* __restrict__ Wu, const float* __restrict__ Wlu,
                           const float* __restrict__ b2, const float* __restrict__ bu) {
    int lane = i & 31;
    if (i < B_FWUE) {
        int r = i >> 8, c = i & 255;
        float s = 0.f;
#pragma unroll 8
        for (int k = 0; k < CH_; k++) s += W2[r * CH_ + k] * g_fWvo[k * CH_ + c];
        g_fW23[i] = s;
    } else if (i < B_B23) {
        int j = i - B_FWUE;
        int r = j >> 10, c = j & 1023;
        float s = Wu[j];
#pragma unroll
        for (int k = 0; k < RANK_; k++) s += g_fT1[r * RANK_ + k] * Wlu[k * C_ + c];
        g_fWuE[j] = s;
    } else if (i < B_BUE) {
        int w = (i - B_B23) >> 5;
        float s = 0.f;
#pragma unroll
        for (int kk = 0; kk < 8; kk++) {
            int k = lane + kk * 32;
            s += b2[k] * g_fWvo[k * CH_ + w];
        }
        s = warp_sum(s);
        if (lane == 0) g_b23[w] = s + g_bvo[w];
    } else if (i < B_TOT) {
        int j = i - B_BUE;
        float s = bu[j];
#pragma unroll
        for (int k = 0; k < RANK_; k++) s += g_t16[k] * Wlu[k * C_ + j];
        g_buE[j] = s;
    }
}

// ---------------- prepC body (dynamic smem; 0.5 folded) -----------------------
__device__ void prepC_body(int e, int tid, char* dsm) {
    if (e < 64) {
        float* As = (float*)dsm;              // [64][33]
        float* Bs = As + 64 * 33;             // [32][65]
        int by = e >> 4, bx = e & 15;
        int ty = tid >> 4, tx = tid & 15;
        float acc[4][4];
#pragma unroll
        for (int a = 0; a < 4; a++)
#pragma unroll
            for (int b = 0; b < 4; b++) acc[a][b] = 0.f;
        for (int kc = 0; kc < 8; kc++) {
#pragma unroll
            for (int j = 0; j < 8; j++) {
                int el = tid + j * 256;
                int m = el >> 5, k = el & 31;
                As[m * 33 + k] = g_fW23[(by * 64 + m) * CH_ + kc * 32 + k];
            }
#pragma unroll
            for (int j = 0; j < 8; j++) {
                int el = tid + j * 256;
                int k = el >> 6, n = el & 63;
                Bs[k * 65 + n] = g_fWuE[(kc * 32 + k) * C_ + bx * 64 + n];
            }
            __syncthreads();
#pragma unroll
            for (int k = 0; k < 32; k++) {
                float a0 = As[(ty * 4 + 0) * 33 + k], a1 = As[(ty * 4 + 1) * 33 + k];
                float a2 = As[(ty * 4 + 2) * 33 + k], a3 = As[(ty * 4 + 3) * 33 + k];
                float b0 = Bs[k * 65 + tx * 4 + 0], b1 = Bs[k * 65 + tx * 4 + 1];
                float b2 = Bs[k * 65 + tx * 4 + 2], b3 = Bs[k * 65 + tx * 4 + 3];
                acc[0][0] += a0 * b0; acc[0][1] += a0 * b1; acc[0][2] += a0 * b2; acc[0][3] += a0 * b3;
                acc[1][0] += a1 * b0; acc[1][1] += a1 * b1; acc[1][2] += a1 * b2; acc[1][3] += a1 * b3;
                acc[2][0] += a2 * b0; acc[2][1] += a2 * b1; acc[2][2] += a2 * b2; acc[2][3] += a2 * b3;
                acc[3][0] += a3 * b0; acc[3][1] += a3 * b1; acc[3][2] += a3 * b2; acc[3][3] += a3 * b3;
            }
            __syncthreads();
        }
#pragma unroll
        for (int a = 0; a < 4; a++) {
            int row = by * 64 + ty * 4 + a;
#pragma unroll
            for (int b = 0; b < 4; b++) {
                int col = bx * 64 + tx * 4 + b;
                g_Wtb[row * C_ + col] = __float2bfloat16_rn(0.5f * acc[a][b]);
            }
        }
    } else {
        int w = (e - 64) * 8 + (tid >> 5);
        int lane = tid & 31;
        for (int jj = 0; jj < 32; jj++) {
            int j = w * 32 + jj;
            float s = 0.f;
#pragma unroll
            for (int kk = 0; kk < 8; kk++) {
                int k = lane + kk * 32;
                s += g_b23[k] * g_fWuE[k * C_ + j];
            }
            s = warp_sum(s);
            if (lane == 0) g_bt[j] = 0.5f * (s + g_buE[j]);
        }
    }
}

// ---------------- shared GEMM primitives -------------------------------------
__device__ __forceinline__ uint32_t smem_u32(const void* p) {
    return (uint32_t)__cvta_generic_to_shared(p);
}
__device__ __forceinline__ void cp16(uint32_t d, const void* s) {
    asm volatile("cp.async.cg.shared.global [%0], [%1], 16;\n" :: "r"(d), "l"(s));
}
__device__ __forceinline__ void cp_commit() { asm volatile("cp.async.commit_group;\n"); }
__device__ __forceinline__ void cp_wait1()  { asm volatile("cp.async.wait_group 1;\n"); }
__device__ __forceinline__ void cp_wait0()  { asm volatile("cp.async.wait_group 0;\n"); }
__device__ __forceinline__ void ldsm_x4(uint32_t* r, uint32_t a) {
    asm volatile("ldmatrix.sync.aligned.m8n8.x4.shared.b16 {%0,%1,%2,%3}, [%4];\n"
                 : "=r"(r[0]), "=r"(r[1]), "=r"(r[2]), "=r"(r[3]) : "r"(a));
}
__device__ __forceinline__ void ldsm_x4_t(uint32_t* r, uint32_t a) {
    asm volatile("ldmatrix.sync.aligned.m8n8.x4.trans.shared.b16 {%0,%1,%2,%3}, [%4];\n"
                 : "=r"(r[0]), "=r"(r[1]), "=r"(r[2]), "=r"(r[3]) : "r"(a));
}
__device__ __forceinline__ void mma16816(float* c, const uint32_t* a, const uint32_t* b) {
    asm volatile(
        "mma.sync.aligned.m16n8k16.row.col.f32.bf16.bf16.f32 "
        "{%0,%1,%2,%3}, {%4,%5,%6,%7}, {%8,%9}, {%0,%1,%2,%3};\n"
        : "+f"(c[0]), "+f"(c[1]), "+f"(c[2]), "+f"(c[3])
        : "r"(a[0]), "r"(a[1]), "r"(a[2]), "r"(a[3]), "r"(b[0]), "r"(b[1]));
}
__device__ __forceinline__ float gelu_tanh(float t) {
    float t3 = t * t * t;
    return 0.5f * t * (1.0f + tanhf(0.7978845608028654f * (t + 0.044715f * t3)));
}

// ---------------- GEMM body (proven; BK=64, 3-stage, single-sync) -------------
// EPI 1: fused GLU | EPI 2: bias+gelu
// EPI 4: bias + v + 0.5*aux (0.5 folded); REQUIRES K==256 (KT=4). Aux tile is
//        cp.async-staged into freed pipeline stages 1,2 during last 2 K-iters
//        (XOR-swizzled 16B chunks, bounded in-stage). Epilogue computes the
//        output IN PLACE over the aux smem, then flushes with fully-coalesced
//        512B-per-warp row stores (LDS.128 + STG.128).
#define SSTG 32768
#define SB_OFF 16384

template <int EPI>
__device__ void gemm_body(const __nv_bfloat16* __restrict__ A,
                          const __nv_bfloat16* __restrict__ W,
                          int N, int K, int ldOut,
                          const float* __restrict__ bias, const float* __restrict__ bias2,
                          const float* __restrict__ aux, void* __restrict__ Cout,
                          int bx, int by, char* dsm) {
    const int tid  = threadIdx.x;
    const int warp = tid >> 5, lane = tid & 31;
    const int warpM = warp & 1;
    const int warpN = warp >> 1;
    const int bm = by * 128;
    const int bn = bx * 128;
    const uint32_t sb = smem_u32(dsm);

    const int ra = tid >> 3, ca = tid & 7;
    uint32_t aSt[4];
    const __nv_bfloat16* pA[4];
#pragma unroll
    for (int i = 0; i < 4; i++) {
        int r = ra + i * 32;
        aSt[i] = (uint32_t)(r * 64 + ((ca ^ (r & 7)) << 3)) * 2;
        pA[i] = A + (size_t)(bm + r) * K + ca * 8;
    }
    const int kb0 = tid >> 4, cbx = tid & 15;
    uint32_t bSt[4];
    const __nv_bfloat16* pB[4];
#pragma unroll
    for (int i = 0; i < 4; i++) {
        int kb = kb0 + i * 16;
        bSt[i] = (uint32_t)(kb * 128 + ((cbx >> 3) << 6) + (((cbx & 7) ^ (kb & 7)) << 3)) * 2;
        pB[i] = W + (size_t)kb * N + bn + cbx * 8;
    }
    const size_t pbStep = (size_t)64 * N;

    float acc[4][4][4];
#pragma unroll
    for (int a0 = 0; a0 < 4; a0++)
#pragma unroll
        for (int a1 = 0; a1 < 4; a1++)
#pragma unroll
            for (int a2 = 0; a2 < 4; a2++) acc[a0][a1][a2] = 0.f;

    const int l15 = lane & 15, hi = lane >> 4, l7 = lane & 7;
    int rowA[4];
#pragma unroll
    for (int mt = 0; mt < 4; mt++) rowA[mt] = warpM * 64 + mt * 16 + l15;

    const int KT = K >> 6;

#pragma unroll
    for (int t = 0; t < 2; t++) {
        uint32_t base = sb + t * SSTG;
#pragma unroll
        for (int i = 0; i < 4; i++) cp16(base + aSt[i], pA[i] + t * 64);
#pragma unroll
        for (int i = 0; i < 4; i++) cp16(base + SB_OFF + bSt[i], pB[i] + (size_t)t * pbStep);
        cp_commit();
    }

    int sL = 2, sC = 0;
    for (int kt = 0; kt < KT; kt++) {
        cp_wait1();
        __syncthreads();
        if (kt + 2 < KT) {
            uint32_t base = sb + sL * SSTG;
#pragma unroll
            for (int i = 0; i < 4; i++) cp16(base + aSt[i], pA[i] + (kt + 2) * 64);
#pragma unroll
            for (int i = 0; i < 4; i++) cp16(base + SB_OFF + bSt[i], pB[i] + (size_t)(kt + 2) * pbStep);
        } else if (EPI == 4) {
            // stage aux chunk (64 rows x 128 f32 = 32KB) into freed stage sL.
            int chunk = kt - (KT - 2);
            uint32_t base = sb + (uint32_t)sL * SSTG;
            const char* ax = (const char*)(aux + (size_t)(bm + chunk * 64) * ldOut + bn);
#pragma unroll
            for (int r2 = 0; r2 < 8; r2++) {
                int L = r2 * 4096 + tid * 16;
                int row = L >> 9, cbyte = L & 511;          // cbyte: 16B-aligned
                cp16(base + (uint32_t)(row * 512 + (cbyte ^ ((row & 7) << 4))),
                     ax + (size_t)row * ldOut * 4 + cbyte);
            }
        }
        cp_commit();

        const uint32_t sA = sb + sC * SSTG;
        const uint32_t sB = sA + SB_OFF;
#pragma unroll
        for (int ks = 0; ks < 4; ks++) {
            uint32_t aF[4][4];
#pragma unroll
            for (int mt = 0; mt < 4; mt++) {
                uint32_t addr = sA + (uint32_t)(rowA[mt] * 64 +
                                  (((ks * 2 + hi) ^ (rowA[mt] & 7)) << 3)) * 2;
                ldsm_x4(aF[mt], addr);
            }
            uint32_t bF[8];
#pragma unroll
            for (int half = 0; half < 2; half++) {
                int c0 = warpN * 4 + half * 2;
                uint32_t addr = sB + (uint32_t)((ks * 16 + l15) * 128 +
                                  (((c0 + hi) ^ l7) << 3)) * 2;
                ldsm_x4_t(&bF[half * 4], addr);
            }
#pragma unroll
            for (int mt = 0; mt < 4; mt++)
#pragma unroll
                for (int nt = 0; nt < 4; nt++)
                    mma16816(acc[mt][nt], aF[mt], &bF[nt * 2]);
        }
        sL = (sL == 2) ? 0 : sL + 1;
        sC = (sC == 2) ? 0 : sC + 1;
    }

    const int g = lane >> 2, tig = lane & 3;

    if (EPI == 1) {
#pragma unroll
        for (int mt = 0; mt < 4; mt++) {
#pragma unroll
            for (int j = 0; j < 2; j++) {
                int F = bn + warpN * 32 + j * 16 + tig * 2;
                int oc = ((F >> 4) << 3) + (F & 7);
                float bdc0 = bias2[oc], bdc1 = bias2[oc + 1];
                float bgc0 = bias[oc],  bgc1 = bias[oc + 1];
#pragma unroll
                for (int h = 0; h < 2; h++) {
                    int row = bm + warpM * 64 + mt * 16 + g + h * 8;
                    float d0 = acc[mt][2 * j][2 * h]     + bdc0;
                    float d1 = acc[mt][2 * j][2 * h + 1] + bdc1;
                    float g0 = acc[mt][2 * j + 1][2 * h]     + bgc0;
                    float g1 = acc[mt][2 * j + 1][2 * h + 1] + bgc1;
                    float s0 = 1.0f / (1.0f + expf(-g0));
                    float s1 = 1.0f / (1.0f + expf(-g1));
                    __nv_bfloat162 o;
                    o.x = __float2bfloat16_rn(d0 * s0);
                    o.y = __float2bfloat16_rn(d1 * s1);
                    *reinterpret_cast<__nv_bfloat162*>((__nv_bfloat16*)Cout +
                        (size_t)row * ldOut + oc) = o;
                }
            }
        }
    } else if (EPI == 2) {
#pragma unroll
        for (int mt = 0; mt < 4; mt++) {
#pragma unroll
            for (int nt = 0; nt < 4; nt++) {
                int col = bn + warpN * 32 + nt * 8 + tig * 2;
#pragma unroll
                for (int h = 0; h < 2; h++) {
                    int row = bm + warpM * 64 + mt * 16 + g + h * 8;
                    float v0 = acc[mt][nt][2 * h], v1 = acc[mt][nt][2 * h + 1];
                    size_t oi = (size_t)row * ldOut + col;
                    __nv_bfloat162 o;
                    o.x = __float2bfloat16_rn(gelu_tanh(v0 + bias[col]));
                    o.y = __float2bfloat16_rn(gelu_tanh(v1 + bias[col + 1]));
                    *reinterpret_cast<__nv_bfloat162*>((__nv_bfloat16*)Cout + oi) = o;
                }
            }
        }
    } else {  // EPI == 4
        cp_wait0();
        __syncthreads();
        // phase 1: compute result in place over staged aux smem
#pragma unroll
        for (int mt = 0; mt < 4; mt++) {
#pragma unroll
            for (int nt = 0; nt < 4; nt++) {
                int coloff = warpN * 32 + nt * 8 + tig * 2;
                int col = bn + coloff;
                int co = coloff * 4, chunk16 = co & ~15, rem = co & 15;
#pragma unroll
                for (int h = 0; h < 2; h++) {
                    int arow = warpM * 64 + mt * 16 + g + h * 8;   // 0..127
                    int w64 = arow & 63;
                    float2* a2p = (float2*)(dsm +
                        (size_t)(1 + (arow >> 6)) * SSTG +
                        w64 * 512 + (chunk16 ^ ((w64 & 7) << 4)) + rem);
                    float2 a2 = *a2p;
                    a2.x = acc[mt][nt][2 * h]     + bias[col]     + 0.5f * a2.x;
                    a2.y = acc[mt][nt][2 * h + 1] + bias[col + 1] + 0.5f * a2.y;
                    *a2p = a2;
                }
            }
        }
        __syncthreads();
        // phase 2: coalesced flush — each warp stores one full 512B row/iter
#pragma unroll
        for (int rr = 0; rr < 16; rr++) {
            int row = warp + rr * 8;                  // 0..127
            int w64 = row & 63;
            const float4* src = (const float4*)(dsm +
                (size_t)(1 + (row >> 6)) * SSTG +
                w64 * 512 + ((lane * 16) ^ ((w64 & 7) << 4)));
            float4 val = *src;
            *reinterpret_cast<float4*>((float*)Cout +
                (size_t)(bm + row) * ldOut + bn + lane * 4) = val;
        }
    }
}

// ---------------- K2: GLU GEMM + prepB ----------------------------------------
__global__ __launch_bounds__(256, 2)
void k2_glu_prepB(const __nv_bfloat16* __restrict__ A, const __nv_bfloat16* __restrict__ W,
                  const float* __restrict__ bg, const float* __restrict__ bd,
                  __nv_bfloat16* __restrict__ out,
                  const float* __restrict__ W2, const float* __restrict__ Wu,
                  const float* __restrict__ Wlu, const float* __restrict__ b2,
                  const float* __restrict__ bu) {
    extern __shared__ __align__(1024) char dsm[];
    if (blockIdx.y < 256) {
        gemm_body<1>(A, W, 512, C_, CH_, bg, bd, nullptr, out,
                     blockIdx.x, blockIdx.y, dsm);
    } else {
        int e = (blockIdx.y - 256) * 4 + blockIdx.x;
        if (e < B_BLOCKS) prepB_body(e * 256 + threadIdx.x, W2, Wu, Wlu, b2, bu);
    }
}

// ---------------- K3: gelu GEMM + prepC ---------------------------------------
__global__ __launch_bounds__(256, 2)
void k3_gelu_prepC(const __nv_bfloat16* __restrict__ A, const __nv_bfloat16* __restrict__ W,
                   const float* __restrict__ b1p, __nv_bfloat16* __restrict__ out) {
    extern __shared__ __align__(1024) char dsm[];
    if (blockIdx.y < 256) {
        gemm_body<2>(A, W, CH_, CH_, CH_, b1p, nullptr, nullptr, out,
                     blockIdx.x, blockIdx.y, dsm);
    } else {
        int e = (blockIdx.y - 256) * 2 + blockIdx.x;
        if (e < 68) prepC_body(e, threadIdx.x, dsm);
    }
}

// ---------------- K4: tail GEMM + residual ------------------------------------
__global__ __launch_bounds__(256, 2)
void k4_tail(const __nv_bfloat16* __restrict__ A, const __nv_bfloat16* __restrict__ W,
             const float* __restrict__ bt, const float* __restrict__ x,
             float* __restrict__ out) {
    extern __shared__ __align__(1024) char dsm[];
    gemm_body<4>(A, W, C_, CH_, C_, bt, nullptr, x, out,
                 blockIdx.x, blockIdx.y, dsm);
}

// ---------------- launch ------------------------------------------------------
static void* sym(const void* s) {
    void* p = nullptr;
    cudaGetSymbolAddress(&p, s);
    return p;
}

extern "C" void kernel_launch(void* const* d_in, const int* in_sizes, int n_in,
                              void* d_out, int out_size) {
    const float* x    = (const float*)d_in[0];
    const float* ln_g = (const float*)d_in[1];
    const float* ln_b = (const float*)d_in[2];
    const float* Wd   = (const float*)d_in[3];
    const float* bd   = (const float*)d_in[4];
    const float* Wg   = (const float*)d_in[5];
    const float* bg   = (const float*)d_in[6];
    const float* dw_w = (const float*)d_in[7];
    const float* dw_b = (const float*)d_in[8];
    const float* W1   = (const float*)d_in[9];
    const float* b1   = (const float*)d_in[10];
    const float* W2   = (const float*)d_in[11];
    const float* b2   = (const float*)d_in[12];
    // d_in[13..16] = Wq,bq,Wk,bk : dead (softmax over one key == 1)
    const float* Wv   = (const float*)d_in[17];
    const float* bv   = (const float*)d_in[18];
    const float* Wo   = (const float*)d_in[19];
    const float* bo   = (const float*)d_in[20];
    const float* Wu   = (const float*)d_in[21];
    const float* bu   = (const float*)d_in[22];
    const float* Wld  = (const float*)d_in[23];
    const float* Wlu  = (const float*)d_in[24];
    float* out = (float*)d_out;

    __nv_bfloat16* zW   = (__nv_bfloat16*)sym(g_z);
    __nv_bfloat16* uW   = (__nv_bfloat16*)sym(g_u);
    __nv_bfloat16* pW   = (__nv_bfloat16*)sym(g_p);
    __nv_bfloat16* Wglu = (__nv_bfloat16*)sym(g_Wglu);
    __nv_bfloat16* W1b  = (__nv_bfloat16*)sym(g_W1b);
    __nv_bfloat16* Wtb  = (__nv_bfloat16*)sym(g_Wtb);
    float* b1p = (float*)sym(g_b1p);
    float* bt  = (float*)sym(g_bt);

    const int SM34 = 3 * SSTG;
    cudaFuncSetAttribute(k2_glu_prepB, cudaFuncAttributeMaxDynamicSharedMemorySize, SM34);
    cudaFuncSetAttribute(k3_gelu_prepC, cudaFuncAttributeMaxDynamicSharedMemorySize, SM34);
    cudaFuncSetAttribute(k4_tail, cudaFuncAttributeMaxDynamicSharedMemorySize, SM34);

    // K1: LN + prepA
    k1_prepA_ln<<<LN_BLOCKS + A_BLOCKS, 256>>>(Wv, Wo, bo, Wu, Wld, dw_w, dw_b, W1, b1,
                                               bv, bu, Wd, Wg, x, ln_g, ln_b, zW);

    // K2: GLU GEMM (4 x 256) + prepB (4 x 329)
    k2_glu_prepB<<<dim3(4, 256 + 329), 256, SM34>>>(zW, Wglu, bg, bd, uW,
                                                    W2, Wu, Wlu, b2, bu);

    // K3: gelu GEMM (2 x 256) + prepC (2 x 34)
    k3_gelu_prepC<<<dim3(2, 256 + 34), 256, SM34>>>(uW, W1b, b1p, pW);

    // K4: tail GEMM + residual (in-place smem epilogue + coalesced flush)
    k4_tail<<<dim3(8, 256), 256, SM34>>>(pW, Wtb, bt, x, out);
}

// round 16
// speedup vs baseline: 1.0157x; 1.0157x over previous
#include <cuda_runtime.h>
#include <cuda_bf16.h>
#include <math.h>
#include <stdint.h>

#define B_  32768
#define C_  1024
#define CH_ 256
#define RANK_ 16

// ---------------- scratch (device globals; no allocation allowed) ------------
__device__ __nv_bfloat16 g_z [B_ * C_];     // LN output
__device__ __nv_bfloat16 g_u [B_ * CH_];    // GLU output
__device__ __nv_bfloat16 g_p [B_ * CH_];    // gelu output

__device__ __nv_bfloat16 g_Wglu[C_ * 512];  // [K=1024][512] interleaved 8d|8g per 16
__device__ __nv_bfloat16 g_W1b [CH_ * CH_]; // [K=256][N=256] dw-folded W1
__device__ __nv_bfloat16 g_Wtb [CH_ * C_];  // [K=256][N=1024] 0.5*Wtail (bf16)

__device__ float g_fWvo[CH_ * CH_];
__device__ float g_fW23[CH_ * CH_];
__device__ float g_fT1 [CH_ * RANK_];
__device__ float g_fWuE[CH_ * C_];
__device__ float g_b1p[CH_], g_bvo[CH_], g_t16[RANK_], g_b23[CH_], g_buE[C_], g_bt[C_];

__device__ __forceinline__ float warp_sum(float s) {
#pragma unroll
    for (int o = 16; o; o >>= 1) s += __shfl_xor_sync(0xFFFFFFFFu, s, o);
    return s;
}

// ---------------- prepA body --------------------------------------------------
#define A_FWVO 0
#define A_FT1  65536
#define A_B1P  196608
#define A_BVO  204800
#define A_T16  212992
#define A_W1B  213504
#define A_WGLU 279040
#define A_TOT  803328
#define A_BLOCKS (A_TOT / 256)   // 3138
#define LN_BLOCKS (B_ / 8)       // 4096

__device__ void prepA_body(int i,
                      const float* __restrict__ Wv, const float* __restrict__ Wo,
                      const float* __restrict__ bo, const float* __restrict__ Wu,
                      const float* __restrict__ Wld, const float* __restrict__ dw_w,
                      const float* __restrict__ dw_b, const float* __restrict__ W1,
                      const float* __restrict__ b1, const float* __restrict__ bv,
                      const float* __restrict__ bu, const float* __restrict__ Wd,
                      const float* __restrict__ Wg) {
    int lane = i & 31;
    if (i < A_FT1) {
        int r = i >> 8, c = i & 255;
        float s = 0.f;
#pragma unroll 8
        for (int k = 0; k < CH_; k++) s += Wv[r * CH_ + k] * Wo[k * CH_ + c];
        g_fWvo[i] = s;
    } else if (i < A_B1P) {
        int w = (i - A_FT1) >> 5;
        int r = w >> 4, c = w & 15;
        float s = 0.f;
#pragma unroll
        for (int kk = 0; kk < 32; kk++) {
            int k = lane + kk * 32;
            s += Wu[r * C_ + k] * Wld[k * RANK_ + c];
        }
        s = warp_sum(s);
        if (lane == 0) g_fT1[w] = s;
    } else if (i < A_BVO) {
        int w = (i - A_B1P) >> 5;
        float s = 0.f;
#pragma unroll
        for (int kk = 0; kk < 8; kk++) {
            int k = lane + kk * 32;
            s += dw_b[k] * W1[k * CH_ + w];
        }
        s = warp_sum(s);
        if (lane == 0) g_b1p[w] = s + b1[w];
    } else if (i < A_T16) {
        int w = (i - A_BVO) >> 5;
        float s = 0.f;
#pragma unroll
        for (int kk = 0; kk < 8; kk++) {
            int k = lane + kk * 32;
            s += bv[k] * Wo[k * CH_ + w];
        }
        s = warp_sum(s);
        if (lane == 0) g_bvo[w] = s + bo[w];
    } else if (i < A_W1B) {
        int w = (i - A_T16) >> 5;
        float s = 0.f;
#pragma unroll
        for (int kk = 0; kk < 32; kk++) {
            int k = lane + kk * 32;
            s += bu[k] * Wld[k * RANK_ + w];
        }
        s = warp_sum(s);
        if (lane == 0) g_t16[w] = s;
    } else if (i < A_WGLU) {
        int j = i - A_W1B;
        int k = j >> 8, n = j & 255;
        g_W1b[j] = __float2bfloat16_rn(dw_w[k] * W1[k * CH_ + n]);
    } else if (i < A_TOT) {
        int j = i - A_WGLU;
        int k = j >> 9, F = j & 511;
        int grp = F >> 4, wi = F & 15;
        int col = grp * 8 + (wi & 7);
        float v = (wi < 8) ? Wd[k * CH_ + col] : Wg[k * CH_ + col];
        g_Wglu[j] = __float2bfloat16_rn(v);
    }
}

// ---------------- LN body: warp-per-row ---------------------------------------
__device__ void ln_body(int w, int lane,
                        const float* __restrict__ x, const float* __restrict__ gamma,
                        const float* __restrict__ beta, __nv_bfloat16* __restrict__ z) {
    const float4* px = (const float4*)(x + (size_t)w * C_);
    float4 v[8];
#pragma unroll
    for (int j = 0; j < 8; j++) v[j] = px[lane + j * 32];
    float s = 0.f, ss = 0.f;
#pragma unroll
    for (int j = 0; j < 8; j++) {
        s  += v[j].x + v[j].y + v[j].z + v[j].w;
        ss += v[j].x * v[j].x + v[j].y * v[j].y + v[j].z * v[j].z + v[j].w * v[j].w;
    }
    s  = warp_sum(s);
    ss = warp_sum(ss);
    float mean = s * (1.f / C_);
    float var  = ss * (1.f / C_) - mean * mean;
    float rstd = rsqrtf(var + 1e-5f);
    uint2* pz = (uint2*)(z + (size_t)w * C_);
    const float4* pg = (const float4*)gamma;
    const float4* pb = (const float4*)beta;
#pragma unroll
    for (int j = 0; j < 8; j++) {
        float4 gm = pg[lane + j * 32];
        float4 bt = pb[lane + j * 32];
        union { __nv_bfloat16 h[4]; uint2 u; } pk;
        pk.h[0] = __float2bfloat16_rn((v[j].x - mean) * rstd * gm.x + bt.x);
        pk.h[1] = __float2bfloat16_rn((v[j].y - mean) * rstd * gm.y + bt.y);
        pk.h[2] = __float2bfloat16_rn((v[j].z - mean) * rstd * gm.z + bt.z);
        pk.h[3] = __float2bfloat16_rn((v[j].w - mean) * rstd * gm.w + bt.w);
        pz[lane + j * 32] = pk.u;
    }
}

// ---------------- K1: LN + prepA ----------------------------------------------
__global__ __launch_bounds__(256)
void k1_prepA_ln(const float* __restrict__ Wv, const float* __restrict__ Wo,
                 const float* __restrict__ bo, const float* __restrict__ Wu,
                 const float* __restrict__ Wld, const float* __restrict__ dw_w,
                 const float* __restrict__ dw_b, const float* __restrict__ W1,
                 const float* __restrict__ b1, const float* __restrict__ bv,
                 const float* __restrict__ bu, const float* __restrict__ Wd,
                 const float* __restrict__ Wg,
                 const float* __restrict__ x, const float* __restrict__ ln_g,
                 const float* __restrict__ ln_b, __nv_bfloat16* __restrict__ z) {
    int bid = blockIdx.x;
    if (bid < LN_BLOCKS) {
        int w = bid * 8 + (threadIdx.x >> 5);
        ln_body(w, threadIdx.x & 31, x, ln_g, ln_b, z);
    } else {
        prepA_body((bid - LN_BLOCKS) * 256 + threadIdx.x, Wv, Wo, bo, Wu, Wld,
                   dw_w, dw_b, W1, b1, bv, bu, Wd, Wg);
    }
}

// ---------------- prepB body --------------------------------------------------
#define B_FWUE 65536
#define B_B23  327680
#define B_BUE  335872
#define B_TOT  336896
#define B_BLOCKS (B_TOT / 256)   // 1316

__device__ void prepB_body(int i, const float* __restrict__ W2,
                           const float* __restrict__ Wu, const float* __restrict__ Wlu,
                           const float* __restrict__ b2, const float* __restrict__ bu) {
    int lane = i & 31;
    if (i < B_FWUE) {
        int r = i >> 8, c = i & 255;
        float s = 0.f;
#pragma unroll 8
        for (int k = 0; k < CH_; k++) s += W2[r * CH_ + k] * g_fWvo[k * CH_ + c];
        g_fW23[i] = s;
    } else if (i < B_B23) {
        int j = i - B_FWUE;
        int r = j >> 10, c = j & 1023;
        float s = Wu[j];
#pragma unroll
        for (int k = 0; k < RANK_; k++) s += g_fT1[r * RANK_ + k] * Wlu[k * C_ + c];
        g_fWuE[j] = s;
    } else if (i < B_BUE) {
        int w = (i - B_B23) >> 5;
        float s = 0.f;
#pragma unroll
        for (int kk = 0; kk < 8; kk++) {
            int k = lane + kk * 32;
            s += b2[k] * g_fWvo[k * CH_ + w];
        }
        s = warp_sum(s);
        if (lane == 0) g_b23[w] = s + g_bvo[w];
    } else if (i < B_TOT) {
        int j = i - B_BUE;
        float s = bu[j];
#pragma unroll
        for (int k = 0; k < RANK_; k++) s += g_t16[k] * Wlu[k * C_ + j];
        g_buE[j] = s;
    }
}

// ---------------- prepC body (dynamic smem; 0.5 folded) -----------------------
__device__ void prepC_body(int e, int tid, char* dsm) {
    if (e < 64) {
        float* As = (float*)dsm;              // [64][33]
        float* Bs = As + 64 * 33;             // [32][65]
        int by = e >> 4, bx = e & 15;
        int ty = tid >> 4, tx = tid & 15;
        float acc[4][4];
#pragma unroll
        for (int a = 0; a < 4; a++)
#pragma unroll
            for (int b = 0; b < 4; b++) acc[a][b] = 0.f;
        for (int kc = 0; kc < 8; kc++) {
#pragma unroll
            for (int j = 0; j < 8; j++) {
                int el = tid + j * 256;
                int m = el >> 5, k = el & 31;
                As[m * 33 + k] = g_fW23[(by * 64 + m) * CH_ + kc * 32 + k];
            }
#pragma unroll
            for (int j = 0; j < 8; j++) {
                int el = tid + j * 256;
                int k = el >> 6, n = el & 63;
                Bs[k * 65 + n] = g_fWuE[(kc * 32 + k) * C_ + bx * 64 + n];
            }
            __syncthreads();
#pragma unroll
            for (int k = 0; k < 32; k++) {
                float a0 = As[(ty * 4 + 0) * 33 + k], a1 = As[(ty * 4 + 1) * 33 + k];
                float a2 = As[(ty * 4 + 2) * 33 + k], a3 = As[(ty * 4 + 3) * 33 + k];
                float b0 = Bs[k * 65 + tx * 4 + 0], b1 = Bs[k * 65 + tx * 4 + 1];
                float b2 = Bs[k * 65 + tx * 4 + 2], b3 = Bs[k * 65 + tx * 4 + 3];
                acc[0][0] += a0 * b0; acc[0][1] += a0 * b1; acc[0][2] += a0 * b2; acc[0][3] += a0 * b3;
                acc[1][0] += a1 * b0; acc[1][1] += a1 * b1; acc[1][2] += a1 * b2; acc[1][3] += a1 * b3;
                acc[2][0] += a2 * b0; acc[2][1] += a2 * b1; acc[2][2] += a2 * b2; acc[2][3] += a2 * b3;
                acc[3][0] += a3 * b0; acc[3][1] += a3 * b1; acc[3][2] += a3 * b2; acc[3][3] += a3 * b3;
            }
            __syncthreads();
        }
#pragma unroll
        for (int a = 0; a < 4; a++) {
            int row = by * 64 + ty * 4 + a;
#pragma unroll
            for (int b = 0; b < 4; b++) {
                int col = bx * 64 + tx * 4 + b;
                g_Wtb[row * C_ + col] = __float2bfloat16_rn(0.5f * acc[a][b]);
            }
        }
    } else {
        int w = (e - 64) * 8 + (tid >> 5);
        int lane = tid & 31;
        for (int jj = 0; jj < 32; jj++) {
            int j = w * 32 + jj;
            float s = 0.f;
#pragma unroll
            for (int kk = 0; kk < 8; kk++) {
                int k = lane + kk * 32;
                s += g_b23[k] * g_fWuE[k * C_ + j];
            }
            s = warp_sum(s);
            if (lane == 0) g_bt[j] = 0.5f * (s + g_buE[j]);
        }
    }
}

// ---------------- shared GEMM primitives -------------------------------------
__device__ __forceinline__ uint32_t smem_u32(const void* p) {
    return (uint32_t)__cvta_generic_to_shared(p);
}
__device__ __forceinline__ void cp16(uint32_t d, const void* s) {
    asm volatile("cp.async.cg.shared.global [%0], [%1], 16;\n" :: "r"(d), "l"(s));
}
__device__ __forceinline__ void cp_commit() { asm volatile("cp.async.commit_group;\n"); }
__device__ __forceinline__ void cp_wait1()  { asm volatile("cp.async.wait_group 1;\n"); }
__device__ __forceinline__ void cp_wait0()  { asm volatile("cp.async.wait_group 0;\n"); }
__device__ __forceinline__ void ldsm_x4(uint32_t* r, uint32_t a) {
    asm volatile("ldmatrix.sync.aligned.m8n8.x4.shared.b16 {%0,%1,%2,%3}, [%4];\n"
                 : "=r"(r[0]), "=r"(r[1]), "=r"(r[2]), "=r"(r[3]) : "r"(a));
}
__device__ __forceinline__ void ldsm_x4_t(uint32_t* r, uint32_t a) {
    asm volatile("ldmatrix.sync.aligned.m8n8.x4.trans.shared.b16 {%0,%1,%2,%3}, [%4];\n"
                 : "=r"(r[0]), "=r"(r[1]), "=r"(r[2]), "=r"(r[3]) : "r"(a));
}
__device__ __forceinline__ void mma16816(float* c, const uint32_t* a, const uint32_t* b) {
    asm volatile(
        "mma.sync.aligned.m16n8k16.row.col.f32.bf16.bf16.f32 "
        "{%0,%1,%2,%3}, {%4,%5,%6,%7}, {%8,%9}, {%0,%1,%2,%3};\n"
        : "+f"(c[0]), "+f"(c[1]), "+f"(c[2]), "+f"(c[3])
        : "r"(a[0]), "r"(a[1]), "r"(a[2]), "r"(a[3]), "r"(b[0]), "r"(b[1]));
}
__device__ __forceinline__ float gelu_tanh(float t) {
    float t3 = t * t * t;
    return 0.5f * t * (1.0f + tanhf(0.7978845608028654f * (t + 0.044715f * t3)));
}

// ---------------- GEMM body (proven; BK=64, 3-stage, single-sync) -------------
// EPI 1: fused GLU | EPI 2: bias+gelu
// EPI 4: bias + v + 0.5*aux (0.5 folded); REQUIRES K==256 (KT=4). Aux tile is
//        cp.async-staged into freed pipeline stages 1,2 during last 2 K-iters
//        (XOR-swizzled 16B chunks, bounded in-stage). Epilogue: per-mt batched
//        aux LDS (MLP=8) + direct vectorized stores; bias hoisted once.
#define SSTG 32768
#define SB_OFF 16384

template <int EPI>
__device__ void gemm_body(const __nv_bfloat16* __restrict__ A,
                          const __nv_bfloat16* __restrict__ W,
                          int N, int K, int ldOut,
                          const float* __restrict__ bias, const float* __restrict__ bias2,
                          const float* __restrict__ aux, void* __restrict__ Cout,
                          int bx, int by, char* dsm) {
    const int tid  = threadIdx.x;
    const int warp = tid >> 5, lane = tid & 31;
    const int warpM = warp & 1;
    const int warpN = warp >> 1;
    const int bm = by * 128;
    const int bn = bx * 128;
    const uint32_t sb = smem_u32(dsm);

    const int ra = tid >> 3, ca = tid & 7;
    uint32_t aSt[4];
    const __nv_bfloat16* pA[4];
#pragma unroll
    for (int i = 0; i < 4; i++) {
        int r = ra + i * 32;
        aSt[i] = (uint32_t)(r * 64 + ((ca ^ (r & 7)) << 3)) * 2;
        pA[i] = A + (size_t)(bm + r) * K + ca * 8;
    }
    const int kb0 = tid >> 4, cbx = tid & 15;
    uint32_t bSt[4];
    const __nv_bfloat16* pB[4];
#pragma unroll
    for (int i = 0; i < 4; i++) {
        int kb = kb0 + i * 16;
        bSt[i] = (uint32_t)(kb * 128 + ((cbx >> 3) << 6) + (((cbx & 7) ^ (kb & 7)) << 3)) * 2;
        pB[i] = W + (size_t)kb * N + bn + cbx * 8;
    }
    const size_t pbStep = (size_t)64 * N;

    float acc[4][4][4];
#pragma unroll
    for (int a0 = 0; a0 < 4; a0++)
#pragma unroll
        for (int a1 = 0; a1 < 4; a1++)
#pragma unroll
            for (int a2 = 0; a2 < 4; a2++) acc[a0][a1][a2] = 0.f;

    const int l15 = lane & 15, hi = lane >> 4, l7 = lane & 7;
    int rowA[4];
#pragma unroll
    for (int mt = 0; mt < 4; mt++) rowA[mt] = warpM * 64 + mt * 16 + l15;

    const int KT = K >> 6;

#pragma unroll
    for (int t = 0; t < 2; t++) {
        uint32_t base = sb + t * SSTG;
#pragma unroll
        for (int i = 0; i < 4; i++) cp16(base + aSt[i], pA[i] + t * 64);
#pragma unroll
        for (int i = 0; i < 4; i++) cp16(base + SB_OFF + bSt[i], pB[i] + (size_t)t * pbStep);
        cp_commit();
    }

    int sL = 2, sC = 0;
    for (int kt = 0; kt < KT; kt++) {
        cp_wait1();
        __syncthreads();
        if (kt + 2 < KT) {
            uint32_t base = sb + sL * SSTG;
#pragma unroll
            for (int i = 0; i < 4; i++) cp16(base + aSt[i], pA[i] + (kt + 2) * 64);
#pragma unroll
            for (int i = 0; i < 4; i++) cp16(base + SB_OFF + bSt[i], pB[i] + (size_t)(kt + 2) * pbStep);
        } else if (EPI == 4) {
            // stage aux chunk (64 rows x 128 f32 = 32KB) into freed stage sL.
            int chunk = kt - (KT - 2);
            uint32_t base = sb + (uint32_t)sL * SSTG;
            const char* ax = (const char*)(aux + (size_t)(bm + chunk * 64) * ldOut + bn);
#pragma unroll
            for (int r2 = 0; r2 < 8; r2++) {
                int L = r2 * 4096 + tid * 16;
                int row = L >> 9, cbyte = L & 511;          // cbyte: 16B-aligned
                cp16(base + (uint32_t)(row * 512 + (cbyte ^ ((row & 7) << 4))),
                     ax + (size_t)row * ldOut * 4 + cbyte);
            }
        }
        cp_commit();

        const uint32_t sA = sb + sC * SSTG;
        const uint32_t sB = sA + SB_OFF;
#pragma unroll
        for (int ks = 0; ks < 4; ks++) {
            uint32_t aF[4][4];
#pragma unroll
            for (int mt = 0; mt < 4; mt++) {
                uint32_t addr = sA + (uint32_t)(rowA[mt] * 64 +
                                  (((ks * 2 + hi) ^ (rowA[mt] & 7)) << 3)) * 2;
                ldsm_x4(aF[mt], addr);
            }
            uint32_t bF[8];
#pragma unroll
            for (int half = 0; half < 2; half++) {
                int c0 = warpN * 4 + half * 2;
                uint32_t addr = sB + (uint32_t)((ks * 16 + l15) * 128 +
                                  (((c0 + hi) ^ l7) << 3)) * 2;
                ldsm_x4_t(&bF[half * 4], addr);
            }
#pragma unroll
            for (int mt = 0; mt < 4; mt++)
#pragma unroll
                for (int nt = 0; nt < 4; nt++)
                    mma16816(acc[mt][nt], aF[mt], &bF[nt * 2]);
        }
        sL = (sL == 2) ? 0 : sL + 1;
        sC = (sC == 2) ? 0 : sC + 1;
    }

    const int g = lane >> 2, tig = lane & 3;

    if (EPI == 1) {
#pragma unroll
        for (int mt = 0; mt < 4; mt++) {
#pragma unroll
            for (int j = 0; j < 2; j++) {
                int F = bn + warpN * 32 + j * 16 + tig * 2;
                int oc = ((F >> 4) << 3) + (F & 7);
                float bdc0 = bias2[oc], bdc1 = bias2[oc + 1];
                float bgc0 = bias[oc],  bgc1 = bias[oc + 1];
#pragma unroll
                for (int h = 0; h < 2; h++) {
                    int row = bm + warpM * 64 + mt * 16 + g + h * 8;
                    float d0 = acc[mt][2 * j][2 * h]     + bdc0;
                    float d1 = acc[mt][2 * j][2 * h + 1] + bdc1;
                    float g0 = acc[mt][2 * j + 1][2 * h]     + bgc0;
                    float g1 = acc[mt][2 * j + 1][2 * h + 1] + bgc1;
                    float s0 = 1.0f / (1.0f + expf(-g0));
                    float s1 = 1.0f / (1.0f + expf(-g1));
                    __nv_bfloat162 o;
                    o.x = __float2bfloat16_rn(d0 * s0);
                    o.y = __float2bfloat16_rn(d1 * s1);
                    *reinterpret_cast<__nv_bfloat162*>((__nv_bfloat16*)Cout +
                        (size_t)row * ldOut + oc) = o;
                }
            }
        }
    } else if (EPI == 2) {
#pragma unroll
        for (int mt = 0; mt < 4; mt++) {
#pragma unroll
            for (int nt = 0; nt < 4; nt++) {
                int col = bn + warpN * 32 + nt * 8 + tig * 2;
#pragma unroll
                for (int h = 0; h < 2; h++) {
                    int row = bm + warpM * 64 + mt * 16 + g + h * 8;
                    float v0 = acc[mt][nt][2 * h], v1 = acc[mt][nt][2 * h + 1];
                    size_t oi = (size_t)row * ldOut + col;
                    __nv_bfloat162 o;
                    o.x = __float2bfloat16_rn(gelu_tanh(v0 + bias[col]));
                    o.y = __float2bfloat16_rn(gelu_tanh(v1 + bias[col + 1]));
                    *reinterpret_cast<__nv_bfloat162*>((__nv_bfloat16*)Cout + oi) = o;
                }
            }
        }
    } else {  // EPI == 4
        cp_wait0();
        __syncthreads();
        // hoist bias (invariant across mt): 4 nt x 2 cols
        float bcol[8];
#pragma unroll
        for (int nt = 0; nt < 4; nt++) {
            int col = bn + warpN * 32 + nt * 8 + tig * 2;
            bcol[nt * 2]     = bias[col];
            bcol[nt * 2 + 1] = bias[col + 1];
        }
#pragma unroll
        for (int mt = 0; mt < 4; mt++) {
            // phase a: batched aux loads (8 independent LDS.64)
            float2 ax[8];
#pragma unroll
            for (int nt = 0; nt < 4; nt++) {
                int co = (warpN * 32 + nt * 8 + tig * 2) * 4;
                int chunk16 = co & ~15, rem = co & 15;
#pragma unroll
                for (int h = 0; h < 2; h++) {
                    int arow = warpM * 64 + mt * 16 + g + h * 8;
                    int w64 = arow & 63;
                    ax[nt * 2 + h] = *(const float2*)(dsm +
                        (size_t)(1 + (arow >> 6)) * SSTG +
                        w64 * 512 + (chunk16 ^ ((w64 & 7) << 4)) + rem);
                }
            }
            // phase b: independent compute + stores
#pragma unroll
            for (int nt = 0; nt < 4; nt++) {
                int col = bn + warpN * 32 + nt * 8 + tig * 2;
#pragma unroll
                for (int h = 0; h < 2; h++) {
                    int row = bm + warpM * 64 + mt * 16 + g + h * 8;
                    float2 a2 = ax[nt * 2 + h];
                    float2 o = make_float2(
                        acc[mt][nt][2 * h]     + bcol[nt * 2]     + 0.5f * a2.x,
                        acc[mt][nt][2 * h + 1] + bcol[nt * 2 + 1] + 0.5f * a2.y);
                    *reinterpret_cast<float2*>((float*)Cout +
                        (size_t)row * ldOut + col) = o;
                }
            }
        }
    }
}

// ---------------- K2: GLU GEMM + prepB ----------------------------------------
__global__ __launch_bounds__(256, 2)
void k2_glu_prepB(const __nv_bfloat16* __restrict__ A, const __nv_bfloat16* __restrict__ W,
                  const float* __restrict__ bg, const float* __restrict__ bd,
                  __nv_bfloat16* __restrict__ out,
                  const float* __restrict__ W2, const float* __restrict__ Wu,
                  const float* __restrict__ Wlu, const float* __restrict__ b2,
                  const float* __restrict__ bu) {
    extern __shared__ __align__(1024) char dsm[];
    if (blockIdx.y < 256) {
        gemm_body<1>(A, W, 512, C_, CH_, bg, bd, nullptr, out,
                     blockIdx.x, blockIdx.y, dsm);
    } else {
        int e = (blockIdx.y - 256) * 4 + blockIdx.x;
        if (e < B_BLOCKS) prepB_body(e * 256 + threadIdx.x, W2, Wu, Wlu, b2, bu);
    }
}

// ---------------- K3: gelu GEMM + prepC ---------------------------------------
__global__ __launch_bounds__(256, 2)
void k3_gelu_prepC(const __nv_bfloat16* __restrict__ A, const __nv_bfloat16* __restrict__ W,
                   const float* __restrict__ b1p, __nv_bfloat16* __restrict__ out) {
    extern __shared__ __align__(1024) char dsm[];
    if (blockIdx.y < 256) {
        gemm_body<2>(A, W, CH_, CH_, CH_, b1p, nullptr, nullptr, out,
                     blockIdx.x, blockIdx.y, dsm);
    } else {
        int e = (blockIdx.y - 256) * 2 + blockIdx.x;
        if (e < 68) prepC_body(e, threadIdx.x, dsm);
    }
}

// ---------------- K4: tail GEMM + residual ------------------------------------
__global__ __launch_bounds__(256, 2)
void k4_tail(const __nv_bfloat16* __restrict__ A, const __nv_bfloat16* __restrict__ W,
             const float* __restrict__ bt, const float* __restrict__ x,
             float* __restrict__ out) {
    extern __shared__ __align__(1024) char dsm[];
    gemm_body<4>(A, W, C_, CH_, C_, bt, nullptr, x, out,
                 blockIdx.x, blockIdx.y, dsm);
}

// ---------------- launch ------------------------------------------------------
static void* sym(const void* s) {
    void* p = nullptr;
    cudaGetSymbolAddress(&p, s);
    return p;
}

extern "C" void kernel_launch(void* const* d_in, const int* in_sizes, int n_in,
                              void* d_out, int out_size) {
    const float* x    = (const float*)d_in[0];
    const float* ln_g = (const float*)d_in[1];
    const float* ln_b = (const float*)d_in[2];
    const float* Wd   = (const float*)d_in[3];
    const float* bd   = (const float*)d_in[4];
    const float* Wg   = (const float*)d_in[5];
    const float* bg   = (const float*)d_in[6];
    const float* dw_w = (const float*)d_in[7];
    const float* dw_b = (const float*)d_in[8];
    const float* W1   = (const float*)d_in[9];
    const float* b1   = (const float*)d_in[10];
    const float* W2   = (const float*)d_in[11];
    const float* b2   = (const float*)d_in[12];
    // d_in[13..16] = Wq,bq,Wk,bk : dead (softmax over one key == 1)
    const float* Wv   = (const float*)d_in[17];
    const float* bv   = (const float*)d_in[18];
    const float* Wo   = (const float*)d_in[19];
    const float* bo   = (const float*)d_in[20];
    const float* Wu   = (const float*)d_in[21];
    const float* bu   = (const float*)d_in[22];
    const float* Wld  = (const float*)d_in[23];
    const float* Wlu  = (const float*)d_in[24];
    float* out = (float*)d_out;

    __nv_bfloat16* zW   = (__nv_bfloat16*)sym(g_z);
    __nv_bfloat16* uW   = (__nv_bfloat16*)sym(g_u);
    __nv_bfloat16* pW   = (__nv_bfloat16*)sym(g_p);
    __nv_bfloat16* Wglu = (__nv_bfloat16*)sym(g_Wglu);
    __nv_bfloat16* W1b  = (__nv_bfloat16*)sym(g_W1b);
    __nv_bfloat16* Wtb  = (__nv_bfloat16*)sym(g_Wtb);
    float* b1p = (float*)sym(g_b1p);
    float* bt  = (float*)sym(g_bt);

    const int SM34 = 3 * SSTG;
    cudaFuncSetAttribute(k2_glu_prepB, cudaFuncAttributeMaxDynamicSharedMemorySize, SM34);
    cudaFuncSetAttribute(k3_gelu_prepC, cudaFuncAttributeMaxDynamicSharedMemorySize, SM34);
    cudaFuncSetAttribute(k4_tail, cudaFuncAttributeMaxDynamicSharedMemorySize, SM34);

    // K1: LN + prepA
    k1_prepA_ln<<<LN_BLOCKS + A_BLOCKS, 256>>>(Wv, Wo, bo, Wu, Wld, dw_w, dw_b, W1, b1,
                                               bv, bu, Wd, Wg, x, ln_g, ln_b, zW);

    // K2: GLU GEMM (4 x 256) + prepB (4 x 329)
    k2_glu_prepB<<<dim3(4, 256 + 329), 256, SM34>>>(zW, Wglu, bg, bd, uW,
                                                    W2, Wu, Wlu, b2, bu);

    // K3: gelu GEMM (2 x 256) + prepC (2 x 34)
    k3_gelu_prepC<<<dim3(2, 256 + 34), 256, SM34>>>(uW, W1b, b1p, pW);

    // K4: tail GEMM + residual (staged aux + batched-LDS epilogue)
    k4_tail<<<dim3(8, 256), 256, SM34>>>(pW, Wtb, bt, x, out);
}